// round 10
// baseline (speedup 1.0000x reference)
#include <cuda_runtime.h>
#include <cuda_bf16.h>
#include <cuda_fp16.h>
#include <cstdint>
#include <math.h>

#define BATCH 16
#define SEQ   2048
#define DE    256
#define DA    64
#define MTOT  (BATCH*SEQ)   // 32768

// ---------------- scratch ----------------
__device__ __half g_xh[MTOT * DE];     // 16 MB
__device__ __half g_qh[MTOT * DA];     // 4 MB
__device__ __half g_kh[MTOT * DA];     // 4 MB
__device__ __half g_vh[MTOT * DE];     // 16 MB, key-interleaved [tok/2][d][tok&1]
__device__ __half g_attnh[MTOT * DE];  // 16 MB
__device__ float  g_h[MTOT * DE];      // 32 MB
__device__ __half g_wqt[DA * DE];      // transposed fp16 weights [n][k]
__device__ __half g_wkt[DA * DE];
__device__ __half g_wvt[DE * DE];
__device__ __half g_wlt[DE * DE];
__device__ float  g_sum[DE];
__device__ float  g_sumsq[DE];

// ================= helpers =================
__device__ __forceinline__ uint32_t smem_to_u32(const void* p) {
    uint32_t a;
    asm("{ .reg .u64 t; cvta.to.shared.u64 t, %1; cvt.u32.u64 %0, t; }" : "=r"(a) : "l"(p));
    return a;
}
__device__ __forceinline__ void mma_f16(float* c, const uint32_t* a,
                                        uint32_t b0, uint32_t b1) {
    asm volatile(
        "mma.sync.aligned.m16n8k16.row.col.f32.f16.f16.f32 "
        "{%0,%1,%2,%3}, {%4,%5,%6,%7}, {%8,%9}, {%0,%1,%2,%3};"
        : "+f"(c[0]), "+f"(c[1]), "+f"(c[2]), "+f"(c[3])
        : "r"(a[0]), "r"(a[1]), "r"(a[2]), "r"(a[3]), "r"(b0), "r"(b1));
}
__device__ __forceinline__ void cp_async16(uint32_t dst, const void* src) {
    asm volatile("cp.async.cg.shared.global [%0], [%1], 16;" :: "r"(dst), "l"(src));
}

// ---------------- conversion kernels ----------------
__global__ void conv_x_kernel(const float* __restrict__ x, __half* __restrict__ xh) {
    const int idx = blockIdx.x * 256 + threadIdx.x;     // float4 index
    float4 f = ((const float4*)x)[idx];
    ((__half2*)xh)[idx * 2]     = __floats2half2_rn(f.x, f.y);
    ((__half2*)xh)[idx * 2 + 1] = __floats2half2_rn(f.z, f.w);
}

// all four weights, one launch. W [256,N] fp32 -> Wt [N][256] fp16
__global__ void conv_w_all_kernel(const float* __restrict__ Wq, __half* __restrict__ Wqt,
                                  const float* __restrict__ Wk, __half* __restrict__ Wkt,
                                  const float* __restrict__ Wv, __half* __restrict__ Wvt,
                                  const float* __restrict__ Wl, __half* __restrict__ Wlt) {
    int idx = blockIdx.x * 256 + threadIdx.x;   // [0, 163840)
    const float* W; __half* Wt; int N;
    if (idx < 16384)      { W = Wq; Wt = Wqt; N = DA; }
    else if (idx < 32768) { W = Wk; Wt = Wkt; N = DA; idx -= 16384; }
    else if (idx < 98304) { W = Wv; Wt = Wvt; N = DE; idx -= 32768; }
    else                  { W = Wl; Wt = Wlt; N = DE; idx -= 98304; }
    int n = idx >> 8, kk = idx & 255;
    Wt[idx] = __float2half_rn(W[kk * N + n]);
}

// ---------------- fp16 mma.sync GEMM (unchanged from R9) ----------------
#define HA_H (128*72)
#define HW_H (64*72)
#define GEMMH_SMEM ((2*HA_H + 2*HW_H)*2)   // 55296 bytes

__global__ void __launch_bounds__(256)
gemm_f16_kernel(const __half* __restrict__ A,
                const __half* __restrict__ Wt,
                const float* __restrict__ bias,
                void* __restrict__ Cout, int Ncols, int mode) {
    extern __shared__ __half smg[];
    __half* smA = smg;
    __half* smW = smg + 2 * HA_H;
    const uint32_t sbA = smem_to_u32(smA);
    const uint32_t sbW = smem_to_u32(smW);

    const int tid = threadIdx.x;
    const int lane = tid & 31, w = tid >> 5;
    const int g = lane >> 2, t = lane & 3;
    const int mw = w >> 1, nw = w & 1;
    const int bm = blockIdx.x * 128;
    const int bn = blockIdx.y * 64;

    float c[2][4][4];
    #pragma unroll
    for (int mb = 0; mb < 2; mb++)
        #pragma unroll
        for (int nb = 0; nb < 4; nb++)
            c[mb][nb][0] = c[mb][nb][1] = c[mb][nb][2] = c[mb][nb][3] = 0.f;

    auto issue = [&](int chunk, int stage) {
        const int k0 = chunk * 64;
        #pragma unroll
        for (int i = 0; i < 4; i++) {
            int idx = tid + i * 256;
            int r = idx >> 3, c16 = idx & 7;
            cp_async16(sbA + (uint32_t)(stage * HA_H + r * 72 + c16 * 8) * 2u,
                       A + (size_t)(bm + r) * 256 + k0 + c16 * 8);
        }
        #pragma unroll
        for (int i = 0; i < 2; i++) {
            int idx = tid + i * 256;
            int r = idx >> 3, c16 = idx & 7;
            cp_async16(sbW + (uint32_t)(stage * HW_H + r * 72 + c16 * 8) * 2u,
                       Wt + (size_t)(bn + r) * 256 + k0 + c16 * 8);
        }
    };

    issue(0, 0);
    asm volatile("cp.async.commit_group;" ::: "memory");

    for (int ch = 0; ch < 4; ch++) {
        if (ch + 1 < 4) {
            issue(ch + 1, (ch + 1) & 1);
            asm volatile("cp.async.commit_group;" ::: "memory");
            asm volatile("cp.async.wait_group 1;" ::: "memory");
        } else {
            asm volatile("cp.async.wait_group 0;" ::: "memory");
        }
        __syncthreads();

        const __half* cA = smA + (ch & 1) * HA_H;
        const __half* cW = smW + (ch & 1) * HW_H;

        #pragma unroll
        for (int ks = 0; ks < 4; ks++) {
            uint32_t af[2][4];
            #pragma unroll
            for (int mb = 0; mb < 2; mb++) {
                const __half* p = cA + (mw * 32 + mb * 16 + g) * 72 + ks * 16 + 2 * t;
                af[mb][0] = *(const uint32_t*)p;
                af[mb][1] = *(const uint32_t*)(p + 8 * 72);
                af[mb][2] = *(const uint32_t*)(p + 8);
                af[mb][3] = *(const uint32_t*)(p + 8 * 72 + 8);
            }
            #pragma unroll
            for (int nb = 0; nb < 4; nb++) {
                const __half* p = cW + (nw * 32 + nb * 8 + g) * 72 + ks * 16 + 2 * t;
                uint32_t b0 = *(const uint32_t*)p;
                uint32_t b1 = *(const uint32_t*)(p + 8);
                #pragma unroll
                for (int mb = 0; mb < 2; mb++)
                    mma_f16(c[mb][nb], af[mb], b0, b1);
            }
        }
        __syncthreads();
    }

    #pragma unroll
    for (int nb = 0; nb < 4; nb++) {
        int col = bn + nw * 32 + nb * 8 + 2 * t;
        float b0 = bias[col], b1 = bias[col + 1];
        #pragma unroll
        for (int mb = 0; mb < 2; mb++) {
            int row = bm + mw * 32 + mb * 16 + g;
            float v00 = c[mb][nb][0] + b0, v01 = c[mb][nb][1] + b1;
            float v10 = c[mb][nb][2] + b0, v11 = c[mb][nb][3] + b1;
            if (mode == 0) {
                float* C = (float*)Cout;
                *(float2*)&C[(size_t)row * Ncols + col] = make_float2(v00, v01);
                *(float2*)&C[(size_t)(row + 8) * Ncols + col] = make_float2(v10, v11);
            } else if (mode == 1) {
                __half2* C2 = (__half2*)Cout;
                C2[((size_t)row * Ncols + col) >> 1] = __floats2half2_rn(v00, v01);
                C2[((size_t)(row + 8) * Ncols + col) >> 1] = __floats2half2_rn(v10, v11);
            } else {
                __half* Ch = (__half*)Cout;
                int r2 = row + 8;
                Ch[(size_t)(row >> 1) * 512 + col * 2 + (row & 1)]       = __float2half_rn(v00);
                Ch[(size_t)(row >> 1) * 512 + (col + 1) * 2 + (row & 1)] = __float2half_rn(v01);
                Ch[(size_t)(r2 >> 1) * 512 + col * 2 + (r2 & 1)]         = __float2half_rn(v10);
                Ch[(size_t)(r2 >> 1) * 512 + (col + 1) * 2 + (r2 & 1)]   = __float2half_rn(v11);
            }
        }
    }
}

// ---------------- pipelined fp16 flash attention ----------------
// CTA = 128 queries, 8 warps, 64-key tiles, TRIPLE-buffered K/V, double-buffered P.
// Iteration i: S(i+1) MMAs + PV(i) MMAs back-to-back, exp(i+1) after (latency-hidden).
// One __syncthreads per iteration.
#define KSTRH 72
#define KFH   (64*KSTRH)            // 4608 halfs
#define VSTRW 264
#define VFW   (32*VSTRW)            // 8448 words
#define STGH  (KFH + 2*VFW)         // 21504 halfs per stage
#define PSTRH 72
#define PFH   (128*PSTRH)           // 9216 halfs
#define NTILES (SEQ/64)             // 32
#define ATTN_SMEM (3*STGH*2 + 2*PFH*2 + 256*4)   // 166912 bytes

__global__ void __launch_bounds__(256, 1)
attn_mma_kernel(const __half* __restrict__ q,
                const __half* __restrict__ k,
                const __half* __restrict__ v,
                __half* __restrict__ out) {
    extern __shared__ __half smh[];
    __half* pbuf = smh + 3 * STGH;
    float* smL = (float*)(pbuf + 2 * PFH);
    const uint32_t sbase = smem_to_u32(smh);
    const int tid = threadIdx.x;
    const int lane = tid & 31, w = tid >> 5;
    const int g = lane >> 2, t = lane & 3;
    const int b = blockIdx.y;
    const int q0 = blockIdx.x * 128;

    const int qg = w >> 1, kh = w & 1;   // S-phase mapping
    const int qh = w >> 2, dg = w & 3;   // PV-phase mapping

    const __half* kb = k + (size_t)b * SEQ * DA;
    const __half* vb = v + (size_t)b * SEQ * DE;

    uint32_t qa[2][4][4];
    {
        const __half* qbase = q + (size_t)(b * SEQ + q0 + qg * 32) * DA;
        #pragma unroll
        for (int m = 0; m < 2; m++) {
            const __half* r0 = qbase + (size_t)(m * 16 + g) * DA;
            const __half* r8 = r0 + 8 * DA;
            #pragma unroll
            for (int ks = 0; ks < 4; ks++) {
                qa[m][ks][0] = *(const uint32_t*)(r0 + ks * 16 + 2 * t);
                qa[m][ks][1] = *(const uint32_t*)(r8 + ks * 16 + 2 * t);
                qa[m][ks][2] = *(const uint32_t*)(r0 + ks * 16 + 2 * t + 8);
                qa[m][ks][3] = *(const uint32_t*)(r8 + ks * 16 + 2 * t + 8);
            }
        }
    }

    float o[4][8][4];
    #pragma unroll
    for (int m = 0; m < 4; m++)
        #pragma unroll
        for (int nb = 0; nb < 8; nb++)
            o[m][nb][0] = o[m][nb][1] = o[m][nb][2] = o[m][nb][3] = 0.f;
    float rs[2][2] = {{0.f, 0.f}, {0.f, 0.f}};

    auto issue = [&](int tile, int stage) {
        const uint32_t kd = sbase + (uint32_t)(stage * STGH) * 2u;
        const uint32_t vd = kd + (uint32_t)KFH * 2u;
        const __half* ksrc = kb + (size_t)tile * 64 * DA;
        const __half* vsrc = vb + (size_t)tile * 32 * 512;
        #pragma unroll
        for (int i = 0; i < 2; i++) {
            int idx = tid + i * 256;
            int r = idx >> 3, c16 = idx & 7;
            cp_async16(kd + (uint32_t)(r * KSTRH * 2 + c16 * 16), ksrc + r * 64 + c16 * 8);
        }
        #pragma unroll
        for (int i = 0; i < 8; i++) {
            int idx = tid + i * 256;
            int r = idx >> 6, ch = idx & 63;
            cp_async16(vd + (uint32_t)(r * VSTRW * 4 + ch * 16), vsrc + (size_t)r * 512 + ch * 8);
        }
    };

    // compute S(tile) into c (from K stage tile%3)
    auto do_S = [&](int tile, float c[2][4][4]) {
        const __half* sK = smh + (tile % 3) * STGH;
        #pragma unroll
        for (int m = 0; m < 2; m++)
            #pragma unroll
            for (int nb = 0; nb < 4; nb++)
                c[m][nb][0] = c[m][nb][1] = c[m][nb][2] = c[m][nb][3] = 0.f;
        #pragma unroll
        for (int ks = 0; ks < 4; ks++) {
            #pragma unroll
            for (int nb = 0; nb < 4; nb++) {
                const __half* kr = sK + (kh * 32 + nb * 8 + g) * KSTRH + ks * 16 + 2 * t;
                uint32_t b0 = *(const uint32_t*)kr;
                uint32_t b1 = *(const uint32_t*)(kr + 8);
                mma_f16(c[0][nb], qa[0][ks], b0, b1);
                mma_f16(c[1][nb], qa[1][ks], b0, b1);
            }
        }
    };

    // exp + store P(tile) to pbuf[tile&1]
    auto do_exp = [&](int tile, float c[2][4][4]) {
        __half* smPn = pbuf + (tile & 1) * PFH;
        #pragma unroll
        for (int m = 0; m < 2; m++) {
            __half* pr = smPn + (qg * 32 + m * 16 + g) * PSTRH + kh * 32;
            __half* pr8 = pr + 8 * PSTRH;
            #pragma unroll
            for (int nb = 0; nb < 4; nb++) {
                float e0 = __expf(c[m][nb][0] * 0.015625f);
                float e1 = __expf(c[m][nb][1] * 0.015625f);
                float e2 = __expf(c[m][nb][2] * 0.015625f);
                float e3 = __expf(c[m][nb][3] * 0.015625f);
                rs[m][0] += e0 + e1;
                rs[m][1] += e2 + e3;
                *(__half2*)(pr + nb * 8 + 2 * t) = __floats2half2_rn(e0, e1);
                *(__half2*)(pr8 + nb * 8 + 2 * t) = __floats2half2_rn(e2, e3);
            }
        }
    };

    // ---- prologue: tiles 0 and 1 in flight; S(0) ----
    issue(0, 0);
    asm volatile("cp.async.commit_group;" ::: "memory");
    issue(1, 1);
    asm volatile("cp.async.commit_group;" ::: "memory");
    asm volatile("cp.async.wait_group 1;" ::: "memory");
    __syncthreads();
    {
        float c[2][4][4];
        do_S(0, c);
        do_exp(0, c);
    }

    // ---- mainloop: one sync per iteration ----
    for (int i = 0; i < NTILES; i++) {
        if (i + 1 < NTILES) asm volatile("cp.async.wait_group 0;" ::: "memory");
        __syncthreads();   // P(i) + K/V(i+1) visible; prev iter's compute done
        if (i + 2 < NTILES) {
            issue(i + 2, (i + 2) % 3);
            asm volatile("cp.async.commit_group;" ::: "memory");
        }

        float c[2][4][4];
        if (i + 1 < NTILES) do_S(i + 1, c);

        // PV(i): reads pbuf[i&1] and V stage i%3
        {
            const uint32_t* sVw = (const uint32_t*)(smh + (i % 3) * STGH + KFH);
            const __half* smPc = pbuf + (i & 1) * PFH;
            #pragma unroll
            for (int ks = 0; ks < 4; ks++) {
                uint32_t pf[4][4];
                #pragma unroll
                for (int m = 0; m < 4; m++) {
                    const __half* p0 = smPc + (qh * 64 + m * 16 + g) * PSTRH + ks * 16 + 2 * t;
                    pf[m][0] = *(const uint32_t*)p0;
                    pf[m][1] = *(const uint32_t*)(p0 + 8 * PSTRH);
                    pf[m][2] = *(const uint32_t*)(p0 + 8);
                    pf[m][3] = *(const uint32_t*)(p0 + 8 * PSTRH + 8);
                }
                #pragma unroll
                for (int nb = 0; nb < 8; nb++) {
                    const uint32_t* vw = sVw + (ks * 8 + t) * VSTRW + dg * 64 + nb * 8 + g;
                    uint32_t b0 = vw[0];
                    uint32_t b1 = vw[4 * VSTRW];
                    #pragma unroll
                    for (int m = 0; m < 4; m++)
                        mma_f16(o[m][nb], pf[m], b0, b1);
                }
            }
        }

        if (i + 1 < NTILES) do_exp(i + 1, c);
    }

    // ---- row-sum reduction ----
    #pragma unroll
    for (int m = 0; m < 2; m++)
        #pragma unroll
        for (int r = 0; r < 2; r++) {
            rs[m][r] += __shfl_xor_sync(0xffffffff, rs[m][r], 1);
            rs[m][r] += __shfl_xor_sync(0xffffffff, rs[m][r], 2);
        }
    if (t == 0) {
        #pragma unroll
        for (int m = 0; m < 2; m++)
            #pragma unroll
            for (int r = 0; r < 2; r++)
                smL[kh * 128 + qg * 32 + m * 16 + r * 8 + g] = rs[m][r];
    }
    __syncthreads();

    // ---- epilogue (fp16 out) ----
    #pragma unroll
    for (int m = 0; m < 4; m++) {
        int qrow = qh * 64 + m * 16 + g;
        float inv0 = 1.f / (smL[qrow] + smL[128 + qrow]);
        float inv8 = 1.f / (smL[qrow + 8] + smL[128 + qrow + 8]);
        __half* out0 = out + (size_t)(b * SEQ + q0 + qrow) * DE + dg * 64;
        __half* out8 = out0 + 8 * DE;
        #pragma unroll
        for (int nb = 0; nb < 8; nb++) {
            *(__half2*)(out0 + nb * 8 + 2 * t) =
                __floats2half2_rn(o[m][nb][0] * inv0, o[m][nb][1] * inv0);
            *(__half2*)(out8 + nb * 8 + 2 * t) =
                __floats2half2_rn(o[m][nb][2] * inv8, o[m][nb][3] * inv8);
        }
    }
}

// ---------------- BatchNorm pieces ----------------
__global__ void bn_zero_kernel() {
    int tidx = threadIdx.x;
    g_sum[tidx] = 0.f;
    g_sumsq[tidx] = 0.f;
}

__global__ void bn_stats_kernel(const float* __restrict__ h) {
    const int c = threadIdx.x;
    const int r0 = blockIdx.x * 128;
    float s = 0.f, s2 = 0.f;
    #pragma unroll 4
    for (int r = 0; r < 128; r++) {
        float x = h[(size_t)(r0 + r) * DE + c];
        s += x;
        s2 += x * x;
    }
    atomicAdd(&g_sum[c], s);
    atomicAdd(&g_sumsq[c], s2);
}

__global__ void bn_finalize_kernel(const float* __restrict__ h,
                                   const float* __restrict__ x,
                                   const float* __restrict__ gamma,
                                   const float* __restrict__ beta,
                                   float* __restrict__ y) {
    const int idx = blockIdx.x * 256 + threadIdx.x;
    const int c0 = (idx * 4) & 255;
    const float invM = 1.f / (float)MTOT;
    float4 hv = ((const float4*)h)[idx];
    float4 xv = ((const float4*)x)[idx];
    float r[4];
    float hvv[4] = {hv.x, hv.y, hv.z, hv.w};
    float xvv[4] = {xv.x, xv.y, xv.z, xv.w};
    #pragma unroll
    for (int u = 0; u < 4; u++) {
        int c = c0 + u;
        float mean = g_sum[c] * invM;
        float var = g_sumsq[c] * invM - mean * mean;
        float rsv = rsqrtf(var + 1e-5f);
        float val = (hvv[u] - mean) * rsv * gamma[c] + beta[c];
        r[u] = fmaxf(val, 0.f) + xvv[u];
    }
    float4 ov = {r[0], r[1], r[2], r[3]};
    ((float4*)y)[idx] = ov;
}

// ---------------- launch ----------------
extern "C" void kernel_launch(void* const* d_in, const int* in_sizes, int n_in,
                              void* d_out, int out_size) {
    const float* x     = (const float*)d_in[0];
    const float* Wq    = (const float*)d_in[1];
    const float* bq    = (const float*)d_in[2];
    const float* Wk    = (const float*)d_in[3];
    const float* bk    = (const float*)d_in[4];
    const float* Wv    = (const float*)d_in[5];
    const float* bv    = (const float*)d_in[6];
    const float* Wl    = (const float*)d_in[7];
    const float* bl    = (const float*)d_in[8];
    const float* gamma = (const float*)d_in[9];
    const float* beta  = (const float*)d_in[10];
    float* out = (float*)d_out;

    __half *pxh, *pqh, *pkh, *pvh, *pattnh, *pwqt, *pwkt, *pwvt, *pwlt;
    float *ph;
    cudaGetSymbolAddress((void**)&pxh, g_xh);
    cudaGetSymbolAddress((void**)&pqh, g_qh);
    cudaGetSymbolAddress((void**)&pkh, g_kh);
    cudaGetSymbolAddress((void**)&pvh, g_vh);
    cudaGetSymbolAddress((void**)&pattnh, g_attnh);
    cudaGetSymbolAddress((void**)&pwqt, g_wqt);
    cudaGetSymbolAddress((void**)&pwkt, g_wkt);
    cudaGetSymbolAddress((void**)&pwvt, g_wvt);
    cudaGetSymbolAddress((void**)&pwlt, g_wlt);
    cudaGetSymbolAddress((void**)&ph, g_h);

    cudaFuncSetAttribute(attn_mma_kernel, cudaFuncAttributeMaxDynamicSharedMemorySize,
                         ATTN_SMEM);
    cudaFuncSetAttribute(gemm_f16_kernel, cudaFuncAttributeMaxDynamicSharedMemorySize,
                         GEMMH_SMEM);

    // conversions (2 launches)
    conv_x_kernel<<<(MTOT * DE) / 4 / 256, 256>>>(x, pxh);
    conv_w_all_kernel<<<(2 * DA * DE + 2 * DE * DE) / 256, 256>>>(
        Wq, pwqt, Wk, pwkt, Wv, pwvt, Wl, pwlt);

    // projections (fp16 mma)
    gemm_f16_kernel<<<dim3(MTOT / 128, 1), 256, GEMMH_SMEM>>>(pxh, pwqt, bq, pqh, DA, 1);
    gemm_f16_kernel<<<dim3(MTOT / 128, 1), 256, GEMMH_SMEM>>>(pxh, pwkt, bk, pkh, DA, 1);
    gemm_f16_kernel<<<dim3(MTOT / 128, 4), 256, GEMMH_SMEM>>>(pxh, pwvt, bv, pvh, DE, 2);

    // attention (pipelined fp16 m16n8k16)
    attn_mma_kernel<<<dim3(SEQ / 128, BATCH), 256, ATTN_SMEM>>>(pqh, pkh, pvh, pattnh);

    // h = attn @ Wl + bl
    gemm_f16_kernel<<<dim3(MTOT / 128, 4), 256, GEMMH_SMEM>>>(pattnh, pwlt, bl, ph, DE, 0);

    // batchnorm + relu + residual
    bn_zero_kernel<<<1, 256>>>();
    bn_stats_kernel<<<MTOT / 128, 256>>>(ph);
    bn_finalize_kernel<<<(MTOT * DE) / 4 / 256, 256>>>(ph, x, gamma, beta, out);
}

// round 11
// speedup vs baseline: 1.0656x; 1.0656x over previous
#include <cuda_runtime.h>
#include <cuda_bf16.h>
#include <cuda_fp16.h>
#include <cstdint>
#include <math.h>

#define BATCH 16
#define SEQ   2048
#define DE    256
#define DA    64
#define MTOT  (BATCH*SEQ)   // 32768

// ---------------- scratch ----------------
__device__ __half g_xh[MTOT * DE];     // 16 MB
__device__ __half g_qh[MTOT * DA];     // 4 MB
__device__ __half g_kh[MTOT * DA];     // 4 MB
__device__ __half g_vh[MTOT * DE];     // 16 MB, key-interleaved [tok/2][d][tok&1]
__device__ __half g_attnh[MTOT * DE];  // 16 MB
__device__ float  g_h[MTOT * DE];      // 32 MB
__device__ __half g_wqt[DA * DE];      // transposed fp16 weights [n][k]
__device__ __half g_wkt[DA * DE];
__device__ __half g_wvt[DE * DE];
__device__ __half g_wlt[DE * DE];
__device__ float  g_sum[DE];
__device__ float  g_sumsq[DE];

// ================= helpers =================
__device__ __forceinline__ uint32_t smem_to_u32(const void* p) {
    uint32_t a;
    asm("{ .reg .u64 t; cvta.to.shared.u64 t, %1; cvt.u32.u64 %0, t; }" : "=r"(a) : "l"(p));
    return a;
}
__device__ __forceinline__ void mma_f16(float* c, const uint32_t* a,
                                        uint32_t b0, uint32_t b1) {
    asm volatile(
        "mma.sync.aligned.m16n8k16.row.col.f32.f16.f16.f32 "
        "{%0,%1,%2,%3}, {%4,%5,%6,%7}, {%8,%9}, {%0,%1,%2,%3};"
        : "+f"(c[0]), "+f"(c[1]), "+f"(c[2]), "+f"(c[3])
        : "r"(a[0]), "r"(a[1]), "r"(a[2]), "r"(a[3]), "r"(b0), "r"(b1));
}
__device__ __forceinline__ void cp_async16(uint32_t dst, const void* src) {
    asm volatile("cp.async.cg.shared.global [%0], [%1], 16;" :: "r"(dst), "l"(src));
}

// ---------------- conversion kernels ----------------
__global__ void conv_x_kernel(const float* __restrict__ x, __half* __restrict__ xh) {
    const int idx = blockIdx.x * 256 + threadIdx.x;     // float4 index
    float4 f = ((const float4*)x)[idx];
    ((__half2*)xh)[idx * 2]     = __floats2half2_rn(f.x, f.y);
    ((__half2*)xh)[idx * 2 + 1] = __floats2half2_rn(f.z, f.w);
}

// all four weights, one launch. W [256,N] fp32 -> Wt [N][256] fp16
__global__ void conv_w_all_kernel(const float* __restrict__ Wq, __half* __restrict__ Wqt,
                                  const float* __restrict__ Wk, __half* __restrict__ Wkt,
                                  const float* __restrict__ Wv, __half* __restrict__ Wvt,
                                  const float* __restrict__ Wl, __half* __restrict__ Wlt) {
    int idx = blockIdx.x * 256 + threadIdx.x;   // [0, 163840)
    const float* W; __half* Wt; int N;
    if (idx < 16384)      { W = Wq; Wt = Wqt; N = DA; }
    else if (idx < 32768) { W = Wk; Wt = Wkt; N = DA; idx -= 16384; }
    else if (idx < 98304) { W = Wv; Wt = Wvt; N = DE; idx -= 32768; }
    else                  { W = Wl; Wt = Wlt; N = DE; idx -= 98304; }
    int n = idx >> 8, kk = idx & 255;
    Wt[idx] = __float2half_rn(W[kk * N + n]);
}

// ---------------- fp16 mma.sync GEMM (unchanged from R9) ----------------
#define HA_H (128*72)
#define HW_H (64*72)
#define GEMMH_SMEM ((2*HA_H + 2*HW_H)*2)   // 55296 bytes

__global__ void __launch_bounds__(256)
gemm_f16_kernel(const __half* __restrict__ A,
                const __half* __restrict__ Wt,
                const float* __restrict__ bias,
                void* __restrict__ Cout, int Ncols, int mode) {
    extern __shared__ __half smg[];
    __half* smA = smg;
    __half* smW = smg + 2 * HA_H;
    const uint32_t sbA = smem_to_u32(smA);
    const uint32_t sbW = smem_to_u32(smW);

    const int tid = threadIdx.x;
    const int lane = tid & 31, w = tid >> 5;
    const int g = lane >> 2, t = lane & 3;
    const int mw = w >> 1, nw = w & 1;
    const int bm = blockIdx.x * 128;
    const int bn = blockIdx.y * 64;

    float c[2][4][4];
    #pragma unroll
    for (int mb = 0; mb < 2; mb++)
        #pragma unroll
        for (int nb = 0; nb < 4; nb++)
            c[mb][nb][0] = c[mb][nb][1] = c[mb][nb][2] = c[mb][nb][3] = 0.f;

    auto issue = [&](int chunk, int stage) {
        const int k0 = chunk * 64;
        #pragma unroll
        for (int i = 0; i < 4; i++) {
            int idx = tid + i * 256;
            int r = idx >> 3, c16 = idx & 7;
            cp_async16(sbA + (uint32_t)(stage * HA_H + r * 72 + c16 * 8) * 2u,
                       A + (size_t)(bm + r) * 256 + k0 + c16 * 8);
        }
        #pragma unroll
        for (int i = 0; i < 2; i++) {
            int idx = tid + i * 256;
            int r = idx >> 3, c16 = idx & 7;
            cp_async16(sbW + (uint32_t)(stage * HW_H + r * 72 + c16 * 8) * 2u,
                       Wt + (size_t)(bn + r) * 256 + k0 + c16 * 8);
        }
    };

    issue(0, 0);
    asm volatile("cp.async.commit_group;" ::: "memory");

    for (int ch = 0; ch < 4; ch++) {
        if (ch + 1 < 4) {
            issue(ch + 1, (ch + 1) & 1);
            asm volatile("cp.async.commit_group;" ::: "memory");
            asm volatile("cp.async.wait_group 1;" ::: "memory");
        } else {
            asm volatile("cp.async.wait_group 0;" ::: "memory");
        }
        __syncthreads();

        const __half* cA = smA + (ch & 1) * HA_H;
        const __half* cW = smW + (ch & 1) * HW_H;

        #pragma unroll
        for (int ks = 0; ks < 4; ks++) {
            uint32_t af[2][4];
            #pragma unroll
            for (int mb = 0; mb < 2; mb++) {
                const __half* p = cA + (mw * 32 + mb * 16 + g) * 72 + ks * 16 + 2 * t;
                af[mb][0] = *(const uint32_t*)p;
                af[mb][1] = *(const uint32_t*)(p + 8 * 72);
                af[mb][2] = *(const uint32_t*)(p + 8);
                af[mb][3] = *(const uint32_t*)(p + 8 * 72 + 8);
            }
            #pragma unroll
            for (int nb = 0; nb < 4; nb++) {
                const __half* p = cW + (nw * 32 + nb * 8 + g) * 72 + ks * 16 + 2 * t;
                uint32_t b0 = *(const uint32_t*)p;
                uint32_t b1 = *(const uint32_t*)(p + 8);
                #pragma unroll
                for (int mb = 0; mb < 2; mb++)
                    mma_f16(c[mb][nb], af[mb], b0, b1);
            }
        }
        __syncthreads();
    }

    #pragma unroll
    for (int nb = 0; nb < 4; nb++) {
        int col = bn + nw * 32 + nb * 8 + 2 * t;
        float b0 = bias[col], b1 = bias[col + 1];
        #pragma unroll
        for (int mb = 0; mb < 2; mb++) {
            int row = bm + mw * 32 + mb * 16 + g;
            float v00 = c[mb][nb][0] + b0, v01 = c[mb][nb][1] + b1;
            float v10 = c[mb][nb][2] + b0, v11 = c[mb][nb][3] + b1;
            if (mode == 0) {
                float* C = (float*)Cout;
                *(float2*)&C[(size_t)row * Ncols + col] = make_float2(v00, v01);
                *(float2*)&C[(size_t)(row + 8) * Ncols + col] = make_float2(v10, v11);
            } else if (mode == 1) {
                __half2* C2 = (__half2*)Cout;
                C2[((size_t)row * Ncols + col) >> 1] = __floats2half2_rn(v00, v01);
                C2[((size_t)(row + 8) * Ncols + col) >> 1] = __floats2half2_rn(v10, v11);
            } else {
                __half* Ch = (__half*)Cout;
                int r2 = row + 8;
                Ch[(size_t)(row >> 1) * 512 + col * 2 + (row & 1)]       = __float2half_rn(v00);
                Ch[(size_t)(row >> 1) * 512 + (col + 1) * 2 + (row & 1)] = __float2half_rn(v01);
                Ch[(size_t)(r2 >> 1) * 512 + col * 2 + (r2 & 1)]         = __float2half_rn(v10);
                Ch[(size_t)(r2 >> 1) * 512 + (col + 1) * 2 + (r2 & 1)]   = __float2half_rn(v11);
            }
        }
    }
}

// ---------------- pipelined fp16 flash attention (exp-early, low regs) -----
// CTA = 128 queries, 8 warps, 64-key tiles, TRIPLE-buffered K/V, double-buffered P.
// Per iteration: S(i+1) -> exp(i+1) (c regs die here) -> PV(i).  ONE sync/tile.
#define KSTRH 72
#define KFH   (64*KSTRH)            // 4608 halfs
#define VSTRW 264
#define VFW   (32*VSTRW)            // 8448 words
#define STGH  (KFH + 2*VFW)         // 21504 halfs per stage
#define PSTRH 72
#define PFH   (128*PSTRH)           // 9216 halfs
#define NTILES (SEQ/64)             // 32
#define ATTN_SMEM (3*STGH*2 + 2*PFH*2 + 256*4)   // 166912 bytes

__global__ void __launch_bounds__(256, 1)
attn_mma_kernel(const __half* __restrict__ q,
                const __half* __restrict__ k,
                const __half* __restrict__ v,
                __half* __restrict__ out) {
    extern __shared__ __half smh[];
    __half* pbuf = smh + 3 * STGH;
    float* smL = (float*)(pbuf + 2 * PFH);
    const uint32_t sbase = smem_to_u32(smh);
    const int tid = threadIdx.x;
    const int lane = tid & 31, w = tid >> 5;
    const int g = lane >> 2, t = lane & 3;
    const int b = blockIdx.y;
    const int q0 = blockIdx.x * 128;

    const int qg = w >> 1, kh = w & 1;   // S-phase mapping
    const int qh = w >> 2, dg = w & 3;   // PV-phase mapping

    const __half* kb = k + (size_t)b * SEQ * DA;
    const __half* vb = v + (size_t)b * SEQ * DE;

    uint32_t qa[2][4][4];
    {
        const __half* qbase = q + (size_t)(b * SEQ + q0 + qg * 32) * DA;
        #pragma unroll
        for (int m = 0; m < 2; m++) {
            const __half* r0 = qbase + (size_t)(m * 16 + g) * DA;
            const __half* r8 = r0 + 8 * DA;
            #pragma unroll
            for (int ks = 0; ks < 4; ks++) {
                qa[m][ks][0] = *(const uint32_t*)(r0 + ks * 16 + 2 * t);
                qa[m][ks][1] = *(const uint32_t*)(r8 + ks * 16 + 2 * t);
                qa[m][ks][2] = *(const uint32_t*)(r0 + ks * 16 + 2 * t + 8);
                qa[m][ks][3] = *(const uint32_t*)(r8 + ks * 16 + 2 * t + 8);
            }
        }
    }

    float o[4][8][4];
    #pragma unroll
    for (int m = 0; m < 4; m++)
        #pragma unroll
        for (int nb = 0; nb < 8; nb++)
            o[m][nb][0] = o[m][nb][1] = o[m][nb][2] = o[m][nb][3] = 0.f;
    float rs[2][2] = {{0.f, 0.f}, {0.f, 0.f}};

    auto issue = [&](int tile, int stage) {
        const uint32_t kd = sbase + (uint32_t)(stage * STGH) * 2u;
        const uint32_t vd = kd + (uint32_t)KFH * 2u;
        const __half* ksrc = kb + (size_t)tile * 64 * DA;
        const __half* vsrc = vb + (size_t)tile * 32 * 512;
        #pragma unroll
        for (int i = 0; i < 2; i++) {
            int idx = tid + i * 256;
            int r = idx >> 3, c16 = idx & 7;
            cp_async16(kd + (uint32_t)(r * KSTRH * 2 + c16 * 16), ksrc + r * 64 + c16 * 8);
        }
        #pragma unroll
        for (int i = 0; i < 8; i++) {
            int idx = tid + i * 256;
            int r = idx >> 6, ch = idx & 63;
            cp_async16(vd + (uint32_t)(r * VSTRW * 4 + ch * 16), vsrc + (size_t)r * 512 + ch * 8);
        }
    };

    // S(tile) + exp + store P(tile) -> pbuf[tile&1]; c regs are local (die here)
    auto do_S_exp = [&](int tile) {
        const __half* sK = smh + (tile % 3) * STGH;
        float c[2][4][4];
        #pragma unroll
        for (int m = 0; m < 2; m++)
            #pragma unroll
            for (int nb = 0; nb < 4; nb++)
                c[m][nb][0] = c[m][nb][1] = c[m][nb][2] = c[m][nb][3] = 0.f;
        #pragma unroll
        for (int ks = 0; ks < 4; ks++) {
            #pragma unroll
            for (int nb = 0; nb < 4; nb++) {
                const __half* kr = sK + (kh * 32 + nb * 8 + g) * KSTRH + ks * 16 + 2 * t;
                uint32_t b0 = *(const uint32_t*)kr;
                uint32_t b1 = *(const uint32_t*)(kr + 8);
                mma_f16(c[0][nb], qa[0][ks], b0, b1);
                mma_f16(c[1][nb], qa[1][ks], b0, b1);
            }
        }
        __half* smPn = pbuf + (tile & 1) * PFH;
        #pragma unroll
        for (int m = 0; m < 2; m++) {
            __half* pr = smPn + (qg * 32 + m * 16 + g) * PSTRH + kh * 32;
            __half* pr8 = pr + 8 * PSTRH;
            #pragma unroll
            for (int nb = 0; nb < 4; nb++) {
                float e0 = __expf(c[m][nb][0] * 0.015625f);
                float e1 = __expf(c[m][nb][1] * 0.015625f);
                float e2 = __expf(c[m][nb][2] * 0.015625f);
                float e3 = __expf(c[m][nb][3] * 0.015625f);
                rs[m][0] += e0 + e1;
                rs[m][1] += e2 + e3;
                *(__half2*)(pr + nb * 8 + 2 * t) = __floats2half2_rn(e0, e1);
                *(__half2*)(pr8 + nb * 8 + 2 * t) = __floats2half2_rn(e2, e3);
            }
        }
    };

    // ---- prologue: tiles 0,1 in flight; P(0) ----
    issue(0, 0);
    asm volatile("cp.async.commit_group;" ::: "memory");
    issue(1, 1);
    asm volatile("cp.async.commit_group;" ::: "memory");
    asm volatile("cp.async.wait_group 1;" ::: "memory");
    __syncthreads();
    do_S_exp(0);

    // ---- mainloop: one sync per iteration ----
    for (int i = 0; i < NTILES; i++) {
        if (i + 1 < NTILES) asm volatile("cp.async.wait_group 0;" ::: "memory");
        __syncthreads();   // P(i) visible; K/V(i+1) loaded; PV(i-1) reads done
        if (i + 2 < NTILES) {
            issue(i + 2, (i + 2) % 3);
            asm volatile("cp.async.commit_group;" ::: "memory");
        }

        if (i + 1 < NTILES) do_S_exp(i + 1);   // writes pbuf[(i+1)&1]

        // PV(i): reads pbuf[i&1] and V stage i%3 — independent of do_S_exp
        {
            const uint32_t* sVw = (const uint32_t*)(smh + (i % 3) * STGH + KFH);
            const __half* smPc = pbuf + (i & 1) * PFH;
            #pragma unroll
            for (int ks = 0; ks < 4; ks++) {
                uint32_t pf[4][4];
                #pragma unroll
                for (int m = 0; m < 4; m++) {
                    const __half* p0 = smPc + (qh * 64 + m * 16 + g) * PSTRH + ks * 16 + 2 * t;
                    pf[m][0] = *(const uint32_t*)p0;
                    pf[m][1] = *(const uint32_t*)(p0 + 8 * PSTRH);
                    pf[m][2] = *(const uint32_t*)(p0 + 8);
                    pf[m][3] = *(const uint32_t*)(p0 + 8 * PSTRH + 8);
                }
                #pragma unroll
                for (int nb = 0; nb < 8; nb++) {
                    const uint32_t* vw = sVw + (ks * 8 + t) * VSTRW + dg * 64 + nb * 8 + g;
                    uint32_t b0 = vw[0];
                    uint32_t b1 = vw[4 * VSTRW];
                    #pragma unroll
                    for (int m = 0; m < 4; m++)
                        mma_f16(o[m][nb], pf[m], b0, b1);
                }
            }
        }
    }

    // ---- row-sum reduction ----
    #pragma unroll
    for (int m = 0; m < 2; m++)
        #pragma unroll
        for (int r = 0; r < 2; r++) {
            rs[m][r] += __shfl_xor_sync(0xffffffff, rs[m][r], 1);
            rs[m][r] += __shfl_xor_sync(0xffffffff, rs[m][r], 2);
        }
    if (t == 0) {
        #pragma unroll
        for (int m = 0; m < 2; m++)
            #pragma unroll
            for (int r = 0; r < 2; r++)
                smL[kh * 128 + qg * 32 + m * 16 + r * 8 + g] = rs[m][r];
    }
    __syncthreads();

    // ---- epilogue (fp16 out) ----
    #pragma unroll
    for (int m = 0; m < 4; m++) {
        int qrow = qh * 64 + m * 16 + g;
        float inv0 = 1.f / (smL[qrow] + smL[128 + qrow]);
        float inv8 = 1.f / (smL[qrow + 8] + smL[128 + qrow + 8]);
        __half* out0 = out + (size_t)(b * SEQ + q0 + qrow) * DE + dg * 64;
        __half* out8 = out0 + 8 * DE;
        #pragma unroll
        for (int nb = 0; nb < 8; nb++) {
            *(__half2*)(out0 + nb * 8 + 2 * t) =
                __floats2half2_rn(o[m][nb][0] * inv0, o[m][nb][1] * inv0);
            *(__half2*)(out8 + nb * 8 + 2 * t) =
                __floats2half2_rn(o[m][nb][2] * inv8, o[m][nb][3] * inv8);
        }
    }
}

// ---------------- BatchNorm pieces ----------------
__global__ void bn_zero_kernel() {
    int tidx = threadIdx.x;
    g_sum[tidx] = 0.f;
    g_sumsq[tidx] = 0.f;
}

__global__ void bn_stats_kernel(const float* __restrict__ h) {
    const int c = threadIdx.x;
    const int r0 = blockIdx.x * 128;
    float s = 0.f, s2 = 0.f;
    #pragma unroll 4
    for (int r = 0; r < 128; r++) {
        float x = h[(size_t)(r0 + r) * DE + c];
        s += x;
        s2 += x * x;
    }
    atomicAdd(&g_sum[c], s);
    atomicAdd(&g_sumsq[c], s2);
}

__global__ void bn_finalize_kernel(const float* __restrict__ h,
                                   const float* __restrict__ x,
                                   const float* __restrict__ gamma,
                                   const float* __restrict__ beta,
                                   float* __restrict__ y) {
    const int idx = blockIdx.x * 256 + threadIdx.x;
    const int c0 = (idx * 4) & 255;
    const float invM = 1.f / (float)MTOT;
    float4 hv = ((const float4*)h)[idx];
    float4 xv = ((const float4*)x)[idx];
    float r[4];
    float hvv[4] = {hv.x, hv.y, hv.z, hv.w};
    float xvv[4] = {xv.x, xv.y, xv.z, xv.w};
    #pragma unroll
    for (int u = 0; u < 4; u++) {
        int c = c0 + u;
        float mean = g_sum[c] * invM;
        float var = g_sumsq[c] * invM - mean * mean;
        float rsv = rsqrtf(var + 1e-5f);
        float val = (hvv[u] - mean) * rsv * gamma[c] + beta[c];
        r[u] = fmaxf(val, 0.f) + xvv[u];
    }
    float4 ov = {r[0], r[1], r[2], r[3]};
    ((float4*)y)[idx] = ov;
}

// ---------------- launch ----------------
extern "C" void kernel_launch(void* const* d_in, const int* in_sizes, int n_in,
                              void* d_out, int out_size) {
    const float* x     = (const float*)d_in[0];
    const float* Wq    = (const float*)d_in[1];
    const float* bq    = (const float*)d_in[2];
    const float* Wk    = (const float*)d_in[3];
    const float* bk    = (const float*)d_in[4];
    const float* Wv    = (const float*)d_in[5];
    const float* bv    = (const float*)d_in[6];
    const float* Wl    = (const float*)d_in[7];
    const float* bl    = (const float*)d_in[8];
    const float* gamma = (const float*)d_in[9];
    const float* beta  = (const float*)d_in[10];
    float* out = (float*)d_out;

    __half *pxh, *pqh, *pkh, *pvh, *pattnh, *pwqt, *pwkt, *pwvt, *pwlt;
    float *ph;
    cudaGetSymbolAddress((void**)&pxh, g_xh);
    cudaGetSymbolAddress((void**)&pqh, g_qh);
    cudaGetSymbolAddress((void**)&pkh, g_kh);
    cudaGetSymbolAddress((void**)&pvh, g_vh);
    cudaGetSymbolAddress((void**)&pattnh, g_attnh);
    cudaGetSymbolAddress((void**)&pwqt, g_wqt);
    cudaGetSymbolAddress((void**)&pwkt, g_wkt);
    cudaGetSymbolAddress((void**)&pwvt, g_wvt);
    cudaGetSymbolAddress((void**)&pwlt, g_wlt);
    cudaGetSymbolAddress((void**)&ph, g_h);

    cudaFuncSetAttribute(attn_mma_kernel, cudaFuncAttributeMaxDynamicSharedMemorySize,
                         ATTN_SMEM);
    cudaFuncSetAttribute(gemm_f16_kernel, cudaFuncAttributeMaxDynamicSharedMemorySize,
                         GEMMH_SMEM);

    // conversions (2 launches)
    conv_x_kernel<<<(MTOT * DE) / 4 / 256, 256>>>(x, pxh);
    conv_w_all_kernel<<<(2 * DA * DE + 2 * DE * DE) / 256, 256>>>(
        Wq, pwqt, Wk, pwkt, Wv, pwvt, Wl, pwlt);

    // projections (fp16 mma)
    gemm_f16_kernel<<<dim3(MTOT / 128, 1), 256, GEMMH_SMEM>>>(pxh, pwqt, bq, pqh, DA, 1);
    gemm_f16_kernel<<<dim3(MTOT / 128, 1), 256, GEMMH_SMEM>>>(pxh, pwkt, bk, pkh, DA, 1);
    gemm_f16_kernel<<<dim3(MTOT / 128, 4), 256, GEMMH_SMEM>>>(pxh, pwvt, bv, pvh, DE, 2);

    // attention (pipelined fp16 m16n8k16, exp-early)
    attn_mma_kernel<<<dim3(SEQ / 128, BATCH), 256, ATTN_SMEM>>>(pqh, pkh, pvh, pattnh);

    // h = attn @ Wl + bl
    gemm_f16_kernel<<<dim3(MTOT / 128, 4), 256, GEMMH_SMEM>>>(pattnh, pwlt, bl, ph, DE, 0);

    // batchnorm + relu + residual
    bn_zero_kernel<<<1, 256>>>();
    bn_stats_kernel<<<MTOT / 128, 256>>>(ph);
    bn_finalize_kernel<<<(MTOT * DE) / 4 / 256, 256>>>(ph, x, gamma, beta, out);
}

// round 12
// speedup vs baseline: 1.0935x; 1.0262x over previous
#include <cuda_runtime.h>
#include <cuda_bf16.h>
#include <cuda_fp16.h>
#include <cstdint>
#include <math.h>

#define BATCH 16
#define SEQ   2048
#define DE    256
#define DA    64
#define MTOT  (BATCH*SEQ)   // 32768

// ---------------- scratch ----------------
__device__ __half g_xh[MTOT * DE];     // 16 MB
__device__ __half g_qh[MTOT * DA];     // 4 MB
__device__ __half g_kh[MTOT * DA];     // 4 MB
__device__ __half g_vh[MTOT * DE];     // 16 MB, key-interleaved [tok/2][d][tok&1]
__device__ __half g_attnh[MTOT * DE];  // 16 MB
__device__ float  g_h[MTOT * DE];      // 32 MB
__device__ __half g_wqt[DA * DE];      // transposed fp16 weights [n][k]
__device__ __half g_wkt[DA * DE];
__device__ __half g_wvt[DE * DE];
__device__ __half g_wlt[DE * DE];
__device__ float  g_sum[DE];
__device__ float  g_sumsq[DE];

// ================= helpers =================
__device__ __forceinline__ uint32_t smem_to_u32(const void* p) {
    uint32_t a;
    asm("{ .reg .u64 t; cvta.to.shared.u64 t, %1; cvt.u32.u64 %0, t; }" : "=r"(a) : "l"(p));
    return a;
}
__device__ __forceinline__ void mma_f16(float* c, const uint32_t* a,
                                        uint32_t b0, uint32_t b1) {
    asm volatile(
        "mma.sync.aligned.m16n8k16.row.col.f32.f16.f16.f32 "
        "{%0,%1,%2,%3}, {%4,%5,%6,%7}, {%8,%9}, {%0,%1,%2,%3};"
        : "+f"(c[0]), "+f"(c[1]), "+f"(c[2]), "+f"(c[3])
        : "r"(a[0]), "r"(a[1]), "r"(a[2]), "r"(a[3]), "r"(b0), "r"(b1));
}
__device__ __forceinline__ void cp_async16(uint32_t dst, const void* src) {
    asm volatile("cp.async.cg.shared.global [%0], [%1], 16;" :: "r"(dst), "l"(src));
}

// ---------------- conversion kernels ----------------
__global__ void conv_x_kernel(const float* __restrict__ x, __half* __restrict__ xh) {
    const int idx = blockIdx.x * 256 + threadIdx.x;     // float4 index
    float4 f = ((const float4*)x)[idx];
    ((__half2*)xh)[idx * 2]     = __floats2half2_rn(f.x, f.y);
    ((__half2*)xh)[idx * 2 + 1] = __floats2half2_rn(f.z, f.w);
}

// all four weights + BN counter zeroing, one launch
__global__ void conv_w_all_kernel(const float* __restrict__ Wq, __half* __restrict__ Wqt,
                                  const float* __restrict__ Wk, __half* __restrict__ Wkt,
                                  const float* __restrict__ Wv, __half* __restrict__ Wvt,
                                  const float* __restrict__ Wl, __half* __restrict__ Wlt) {
    int idx = blockIdx.x * 256 + threadIdx.x;   // [0, 163840)
    if (blockIdx.x == 0) {
        g_sum[threadIdx.x] = 0.f;
        g_sumsq[threadIdx.x] = 0.f;
    }
    const float* W; __half* Wt; int N;
    if (idx < 16384)      { W = Wq; Wt = Wqt; N = DA; }
    else if (idx < 32768) { W = Wk; Wt = Wkt; N = DA; idx -= 16384; }
    else if (idx < 98304) { W = Wv; Wt = Wvt; N = DE; idx -= 32768; }
    else                  { W = Wl; Wt = Wlt; N = DE; idx -= 98304; }
    int n = idx >> 8, kk = idx & 255;
    Wt[idx] = __float2half_rn(W[kk * N + n]);
}

// ---------------- fp16 mma.sync GEMM ----------------
// modes: 0 fp32 [row][col] + fused BN stats, 1 fp16 [row][col], 2 fp16 V-interleaved.
// blockIdx.z==1 switches to the secondary (Wt2,bias2,Cout2) problem (q/k merge).
#define HA_H (128*72)
#define HW_H (64*72)
#define GEMMH_SMEM ((2*HA_H + 2*HW_H)*2)   // 55296 bytes

__global__ void __launch_bounds__(256)
gemm_f16_kernel(const __half* __restrict__ A,
                const __half* Wt_, const float* bias_, void* Cout_,
                const __half* Wt2, const float* bias2, void* Cout2,
                int Ncols, int mode) {
    extern __shared__ __half smg[];
    __half* smA = smg;
    __half* smW = smg + 2 * HA_H;
    __shared__ float sred[128];     // fused BN stats buffer (mode 0)
    const uint32_t sbA = smem_to_u32(smA);
    const uint32_t sbW = smem_to_u32(smW);

    const __half* Wt  = (blockIdx.z == 0) ? Wt_ : Wt2;
    const float* bias = (blockIdx.z == 0) ? bias_ : bias2;
    void* Cout        = (blockIdx.z == 0) ? Cout_ : Cout2;

    const int tid = threadIdx.x;
    const int lane = tid & 31, w = tid >> 5;
    const int g = lane >> 2, t = lane & 3;
    const int mw = w >> 1, nw = w & 1;
    const int bm = blockIdx.x * 128;
    const int bn = blockIdx.y * 64;

    if (mode == 0 && tid < 128) sred[tid] = 0.f;

    float c[2][4][4];
    #pragma unroll
    for (int mb = 0; mb < 2; mb++)
        #pragma unroll
        for (int nb = 0; nb < 4; nb++)
            c[mb][nb][0] = c[mb][nb][1] = c[mb][nb][2] = c[mb][nb][3] = 0.f;

    auto issue = [&](int chunk, int stage) {
        const int k0 = chunk * 64;
        #pragma unroll
        for (int i = 0; i < 4; i++) {
            int idx = tid + i * 256;
            int r = idx >> 3, c16 = idx & 7;
            cp_async16(sbA + (uint32_t)(stage * HA_H + r * 72 + c16 * 8) * 2u,
                       A + (size_t)(bm + r) * 256 + k0 + c16 * 8);
        }
        #pragma unroll
        for (int i = 0; i < 2; i++) {
            int idx = tid + i * 256;
            int r = idx >> 3, c16 = idx & 7;
            cp_async16(sbW + (uint32_t)(stage * HW_H + r * 72 + c16 * 8) * 2u,
                       Wt + (size_t)(bn + r) * 256 + k0 + c16 * 8);
        }
    };

    issue(0, 0);
    asm volatile("cp.async.commit_group;" ::: "memory");

    for (int ch = 0; ch < 4; ch++) {
        if (ch + 1 < 4) {
            issue(ch + 1, (ch + 1) & 1);
            asm volatile("cp.async.commit_group;" ::: "memory");
            asm volatile("cp.async.wait_group 1;" ::: "memory");
        } else {
            asm volatile("cp.async.wait_group 0;" ::: "memory");
        }
        __syncthreads();

        const __half* cA = smA + (ch & 1) * HA_H;
        const __half* cW = smW + (ch & 1) * HW_H;

        #pragma unroll
        for (int ks = 0; ks < 4; ks++) {
            uint32_t af[2][4];
            #pragma unroll
            for (int mb = 0; mb < 2; mb++) {
                const __half* p = cA + (mw * 32 + mb * 16 + g) * 72 + ks * 16 + 2 * t;
                af[mb][0] = *(const uint32_t*)p;
                af[mb][1] = *(const uint32_t*)(p + 8 * 72);
                af[mb][2] = *(const uint32_t*)(p + 8);
                af[mb][3] = *(const uint32_t*)(p + 8 * 72 + 8);
            }
            #pragma unroll
            for (int nb = 0; nb < 4; nb++) {
                const __half* p = cW + (nw * 32 + nb * 8 + g) * 72 + ks * 16 + 2 * t;
                uint32_t b0 = *(const uint32_t*)p;
                uint32_t b1 = *(const uint32_t*)(p + 8);
                #pragma unroll
                for (int mb = 0; mb < 2; mb++)
                    mma_f16(c[mb][nb], af[mb], b0, b1);
            }
        }
        __syncthreads();
    }

    float colsum[4][2] = {}, colsq[4][2] = {};

    #pragma unroll
    for (int nb = 0; nb < 4; nb++) {
        int col = bn + nw * 32 + nb * 8 + 2 * t;
        float b0 = bias[col], b1 = bias[col + 1];
        #pragma unroll
        for (int mb = 0; mb < 2; mb++) {
            int row = bm + mw * 32 + mb * 16 + g;
            float v00 = c[mb][nb][0] + b0, v01 = c[mb][nb][1] + b1;
            float v10 = c[mb][nb][2] + b0, v11 = c[mb][nb][3] + b1;
            if (mode == 0) {
                float* C = (float*)Cout;
                *(float2*)&C[(size_t)row * Ncols + col] = make_float2(v00, v01);
                *(float2*)&C[(size_t)(row + 8) * Ncols + col] = make_float2(v10, v11);
                colsum[nb][0] += v00 + v10;
                colsum[nb][1] += v01 + v11;
                colsq[nb][0] += v00 * v00 + v10 * v10;
                colsq[nb][1] += v01 * v01 + v11 * v11;
            } else if (mode == 1) {
                __half2* C2 = (__half2*)Cout;
                C2[((size_t)row * Ncols + col) >> 1] = __floats2half2_rn(v00, v01);
                C2[((size_t)(row + 8) * Ncols + col) >> 1] = __floats2half2_rn(v10, v11);
            } else {
                __half* Ch = (__half*)Cout;
                int r2 = row + 8;
                Ch[(size_t)(row >> 1) * 512 + col * 2 + (row & 1)]       = __float2half_rn(v00);
                Ch[(size_t)(row >> 1) * 512 + (col + 1) * 2 + (row & 1)] = __float2half_rn(v01);
                Ch[(size_t)(r2 >> 1) * 512 + col * 2 + (r2 & 1)]         = __float2half_rn(v10);
                Ch[(size_t)(r2 >> 1) * 512 + (col + 1) * 2 + (r2 & 1)]   = __float2half_rn(v11);
            }
        }
    }

    if (mode == 0) {
        // reduce over g lanes (lane bits 2..4), then across warps via shared atomics
        #pragma unroll
        for (int nb = 0; nb < 4; nb++)
            #pragma unroll
            for (int j = 0; j < 2; j++) {
                float s = colsum[nb][j], q = colsq[nb][j];
                #pragma unroll
                for (int d = 4; d <= 16; d <<= 1) {
                    s += __shfl_xor_sync(0xffffffff, s, d);
                    q += __shfl_xor_sync(0xffffffff, q, d);
                }
                if (g == 0) {
                    int cl = nw * 32 + nb * 8 + 2 * t + j;   // local col [0,64)
                    atomicAdd(&sred[cl * 2],     s);
                    atomicAdd(&sred[cl * 2 + 1], q);
                }
            }
        __syncthreads();
        if (tid < 64) atomicAdd(&g_sum[bn + tid], sred[tid * 2]);
        else if (tid < 128) atomicAdd(&g_sumsq[bn + tid - 64], sred[(tid - 64) * 2 + 1]);
    }
}

// ---------------- pipelined fp16 flash attention (unchanged from R11) -----
#define KSTRH 72
#define KFH   (64*KSTRH)            // 4608 halfs
#define VSTRW 264
#define VFW   (32*VSTRW)            // 8448 words
#define STGH  (KFH + 2*VFW)         // 21504 halfs per stage
#define PSTRH 72
#define PFH   (128*PSTRH)           // 9216 halfs
#define NTILES (SEQ/64)             // 32
#define ATTN_SMEM (3*STGH*2 + 2*PFH*2 + 256*4)   // 166912 bytes

__global__ void __launch_bounds__(256, 1)
attn_mma_kernel(const __half* __restrict__ q,
                const __half* __restrict__ k,
                const __half* __restrict__ v,
                __half* __restrict__ out) {
    extern __shared__ __half smh[];
    __half* pbuf = smh + 3 * STGH;
    float* smL = (float*)(pbuf + 2 * PFH);
    const uint32_t sbase = smem_to_u32(smh);
    const int tid = threadIdx.x;
    const int lane = tid & 31, w = tid >> 5;
    const int g = lane >> 2, t = lane & 3;
    const int b = blockIdx.y;
    const int q0 = blockIdx.x * 128;

    const int qg = w >> 1, kh = w & 1;   // S-phase mapping
    const int qh = w >> 2, dg = w & 3;   // PV-phase mapping

    const __half* kb = k + (size_t)b * SEQ * DA;
    const __half* vb = v + (size_t)b * SEQ * DE;

    uint32_t qa[2][4][4];
    {
        const __half* qbase = q + (size_t)(b * SEQ + q0 + qg * 32) * DA;
        #pragma unroll
        for (int m = 0; m < 2; m++) {
            const __half* r0 = qbase + (size_t)(m * 16 + g) * DA;
            const __half* r8 = r0 + 8 * DA;
            #pragma unroll
            for (int ks = 0; ks < 4; ks++) {
                qa[m][ks][0] = *(const uint32_t*)(r0 + ks * 16 + 2 * t);
                qa[m][ks][1] = *(const uint32_t*)(r8 + ks * 16 + 2 * t);
                qa[m][ks][2] = *(const uint32_t*)(r0 + ks * 16 + 2 * t + 8);
                qa[m][ks][3] = *(const uint32_t*)(r8 + ks * 16 + 2 * t + 8);
            }
        }
    }

    float o[4][8][4];
    #pragma unroll
    for (int m = 0; m < 4; m++)
        #pragma unroll
        for (int nb = 0; nb < 8; nb++)
            o[m][nb][0] = o[m][nb][1] = o[m][nb][2] = o[m][nb][3] = 0.f;
    float rs[2][2] = {{0.f, 0.f}, {0.f, 0.f}};

    auto issue = [&](int tile, int stage) {
        const uint32_t kd = sbase + (uint32_t)(stage * STGH) * 2u;
        const uint32_t vd = kd + (uint32_t)KFH * 2u;
        const __half* ksrc = kb + (size_t)tile * 64 * DA;
        const __half* vsrc = vb + (size_t)tile * 32 * 512;
        #pragma unroll
        for (int i = 0; i < 2; i++) {
            int idx = tid + i * 256;
            int r = idx >> 3, c16 = idx & 7;
            cp_async16(kd + (uint32_t)(r * KSTRH * 2 + c16 * 16), ksrc + r * 64 + c16 * 8);
        }
        #pragma unroll
        for (int i = 0; i < 8; i++) {
            int idx = tid + i * 256;
            int r = idx >> 6, ch = idx & 63;
            cp_async16(vd + (uint32_t)(r * VSTRW * 4 + ch * 16), vsrc + (size_t)r * 512 + ch * 8);
        }
    };

    auto do_S_exp = [&](int tile) {
        const __half* sK = smh + (tile % 3) * STGH;
        float c[2][4][4];
        #pragma unroll
        for (int m = 0; m < 2; m++)
            #pragma unroll
            for (int nb = 0; nb < 4; nb++)
                c[m][nb][0] = c[m][nb][1] = c[m][nb][2] = c[m][nb][3] = 0.f;
        #pragma unroll
        for (int ks = 0; ks < 4; ks++) {
            #pragma unroll
            for (int nb = 0; nb < 4; nb++) {
                const __half* kr = sK + (kh * 32 + nb * 8 + g) * KSTRH + ks * 16 + 2 * t;
                uint32_t b0 = *(const uint32_t*)kr;
                uint32_t b1 = *(const uint32_t*)(kr + 8);
                mma_f16(c[0][nb], qa[0][ks], b0, b1);
                mma_f16(c[1][nb], qa[1][ks], b0, b1);
            }
        }
        __half* smPn = pbuf + (tile & 1) * PFH;
        #pragma unroll
        for (int m = 0; m < 2; m++) {
            __half* pr = smPn + (qg * 32 + m * 16 + g) * PSTRH + kh * 32;
            __half* pr8 = pr + 8 * PSTRH;
            #pragma unroll
            for (int nb = 0; nb < 4; nb++) {
                float e0 = __expf(c[m][nb][0] * 0.015625f);
                float e1 = __expf(c[m][nb][1] * 0.015625f);
                float e2 = __expf(c[m][nb][2] * 0.015625f);
                float e3 = __expf(c[m][nb][3] * 0.015625f);
                rs[m][0] += e0 + e1;
                rs[m][1] += e2 + e3;
                *(__half2*)(pr + nb * 8 + 2 * t) = __floats2half2_rn(e0, e1);
                *(__half2*)(pr8 + nb * 8 + 2 * t) = __floats2half2_rn(e2, e3);
            }
        }
    };

    issue(0, 0);
    asm volatile("cp.async.commit_group;" ::: "memory");
    issue(1, 1);
    asm volatile("cp.async.commit_group;" ::: "memory");
    asm volatile("cp.async.wait_group 1;" ::: "memory");
    __syncthreads();
    do_S_exp(0);

    for (int i = 0; i < NTILES; i++) {
        if (i + 1 < NTILES) asm volatile("cp.async.wait_group 0;" ::: "memory");
        __syncthreads();
        if (i + 2 < NTILES) {
            issue(i + 2, (i + 2) % 3);
            asm volatile("cp.async.commit_group;" ::: "memory");
        }

        if (i + 1 < NTILES) do_S_exp(i + 1);

        {
            const uint32_t* sVw = (const uint32_t*)(smh + (i % 3) * STGH + KFH);
            const __half* smPc = pbuf + (i & 1) * PFH;
            #pragma unroll
            for (int ks = 0; ks < 4; ks++) {
                uint32_t pf[4][4];
                #pragma unroll
                for (int m = 0; m < 4; m++) {
                    const __half* p0 = smPc + (qh * 64 + m * 16 + g) * PSTRH + ks * 16 + 2 * t;
                    pf[m][0] = *(const uint32_t*)p0;
                    pf[m][1] = *(const uint32_t*)(p0 + 8 * PSTRH);
                    pf[m][2] = *(const uint32_t*)(p0 + 8);
                    pf[m][3] = *(const uint32_t*)(p0 + 8 * PSTRH + 8);
                }
                #pragma unroll
                for (int nb = 0; nb < 8; nb++) {
                    const uint32_t* vw = sVw + (ks * 8 + t) * VSTRW + dg * 64 + nb * 8 + g;
                    uint32_t b0 = vw[0];
                    uint32_t b1 = vw[4 * VSTRW];
                    #pragma unroll
                    for (int m = 0; m < 4; m++)
                        mma_f16(o[m][nb], pf[m], b0, b1);
                }
            }
        }
    }

    #pragma unroll
    for (int m = 0; m < 2; m++)
        #pragma unroll
        for (int r = 0; r < 2; r++) {
            rs[m][r] += __shfl_xor_sync(0xffffffff, rs[m][r], 1);
            rs[m][r] += __shfl_xor_sync(0xffffffff, rs[m][r], 2);
        }
    if (t == 0) {
        #pragma unroll
        for (int m = 0; m < 2; m++)
            #pragma unroll
            for (int r = 0; r < 2; r++)
                smL[kh * 128 + qg * 32 + m * 16 + r * 8 + g] = rs[m][r];
    }
    __syncthreads();

    #pragma unroll
    for (int m = 0; m < 4; m++) {
        int qrow = qh * 64 + m * 16 + g;
        float inv0 = 1.f / (smL[qrow] + smL[128 + qrow]);
        float inv8 = 1.f / (smL[qrow + 8] + smL[128 + qrow + 8]);
        __half* out0 = out + (size_t)(b * SEQ + q0 + qrow) * DE + dg * 64;
        __half* out8 = out0 + 8 * DE;
        #pragma unroll
        for (int nb = 0; nb < 8; nb++) {
            *(__half2*)(out0 + nb * 8 + 2 * t) =
                __floats2half2_rn(o[m][nb][0] * inv0, o[m][nb][1] * inv0);
            *(__half2*)(out8 + nb * 8 + 2 * t) =
                __floats2half2_rn(o[m][nb][2] * inv8, o[m][nb][3] * inv8);
        }
    }
}

// ---------------- BN finalize ----------------
__global__ void bn_finalize_kernel(const float* __restrict__ h,
                                   const float* __restrict__ x,
                                   const float* __restrict__ gamma,
                                   const float* __restrict__ beta,
                                   float* __restrict__ y) {
    const int idx = blockIdx.x * 256 + threadIdx.x;
    const int c0 = (idx * 4) & 255;
    const float invM = 1.f / (float)MTOT;
    float4 hv = ((const float4*)h)[idx];
    float4 xv = ((const float4*)x)[idx];
    float r[4];
    float hvv[4] = {hv.x, hv.y, hv.z, hv.w};
    float xvv[4] = {xv.x, xv.y, xv.z, xv.w};
    #pragma unroll
    for (int u = 0; u < 4; u++) {
        int c = c0 + u;
        float mean = g_sum[c] * invM;
        float var = g_sumsq[c] * invM - mean * mean;
        float rsv = rsqrtf(var + 1e-5f);
        float val = (hvv[u] - mean) * rsv * gamma[c] + beta[c];
        r[u] = fmaxf(val, 0.f) + xvv[u];
    }
    float4 ov = {r[0], r[1], r[2], r[3]};
    ((float4*)y)[idx] = ov;
}

// ---------------- launch ----------------
extern "C" void kernel_launch(void* const* d_in, const int* in_sizes, int n_in,
                              void* d_out, int out_size) {
    const float* x     = (const float*)d_in[0];
    const float* Wq    = (const float*)d_in[1];
    const float* bq    = (const float*)d_in[2];
    const float* Wk    = (const float*)d_in[3];
    const float* bk    = (const float*)d_in[4];
    const float* Wv    = (const float*)d_in[5];
    const float* bv    = (const float*)d_in[6];
    const float* Wl    = (const float*)d_in[7];
    const float* bl    = (const float*)d_in[8];
    const float* gamma = (const float*)d_in[9];
    const float* beta  = (const float*)d_in[10];
    float* out = (float*)d_out;

    __half *pxh, *pqh, *pkh, *pvh, *pattnh, *pwqt, *pwkt, *pwvt, *pwlt;
    float *ph;
    cudaGetSymbolAddress((void**)&pxh, g_xh);
    cudaGetSymbolAddress((void**)&pqh, g_qh);
    cudaGetSymbolAddress((void**)&pkh, g_kh);
    cudaGetSymbolAddress((void**)&pvh, g_vh);
    cudaGetSymbolAddress((void**)&pattnh, g_attnh);
    cudaGetSymbolAddress((void**)&pwqt, g_wqt);
    cudaGetSymbolAddress((void**)&pwkt, g_wkt);
    cudaGetSymbolAddress((void**)&pwvt, g_wvt);
    cudaGetSymbolAddress((void**)&pwlt, g_wlt);
    cudaGetSymbolAddress((void**)&ph, g_h);

    cudaFuncSetAttribute(attn_mma_kernel, cudaFuncAttributeMaxDynamicSharedMemorySize,
                         ATTN_SMEM);
    cudaFuncSetAttribute(gemm_f16_kernel, cudaFuncAttributeMaxDynamicSharedMemorySize,
                         GEMMH_SMEM);

    // conversions + BN counter zeroing (2 launches)
    conv_x_kernel<<<(MTOT * DE) / 4 / 256, 256>>>(x, pxh);
    conv_w_all_kernel<<<(2 * DA * DE + 2 * DE * DE) / 256, 256>>>(
        Wq, pwqt, Wk, pwkt, Wv, pwvt, Wl, pwlt);

    // q + k projections merged into one launch (blockIdx.z)
    gemm_f16_kernel<<<dim3(MTOT / 128, 1, 2), 256, GEMMH_SMEM>>>(
        pxh, pwqt, bq, pqh, pwkt, bk, pkh, DA, 1);
    // v projection
    gemm_f16_kernel<<<dim3(MTOT / 128, 4, 1), 256, GEMMH_SMEM>>>(
        pxh, pwvt, bv, pvh, pwvt, bv, pvh, DE, 2);

    // attention (pipelined fp16 m16n8k16)
    attn_mma_kernel<<<dim3(SEQ / 128, BATCH), 256, ATTN_SMEM>>>(pqh, pkh, pvh, pattnh);

    // h = attn @ Wl + bl, with fused BN statistics
    gemm_f16_kernel<<<dim3(MTOT / 128, 4, 1), 256, GEMMH_SMEM>>>(
        pattnh, pwlt, bl, ph, pwlt, bl, ph, DE, 0);

    // batchnorm finalize + relu + residual
    bn_finalize_kernel<<<(MTOT * DE) / 4 / 256, 256>>>(ph, x, gamma, beta, out);
}

// round 14
// speedup vs baseline: 1.1350x; 1.0380x over previous
#include <cuda_runtime.h>
#include <cuda_bf16.h>
#include <cuda_fp16.h>
#include <cstdint>
#include <math.h>

#define BATCH 16
#define SEQ   2048
#define DE    256
#define DA    64
#define MTOT  (BATCH*SEQ)   // 32768

// ---------------- scratch ----------------
__device__ __half g_xh[MTOT * DE];     // 16 MB
__device__ __half g_qh[MTOT * DA];     // 4 MB
__device__ __half g_kh[MTOT * DA];     // 4 MB
__device__ __half g_vh[MTOT * DE];     // 16 MB, key-interleaved [tok/2][d][tok&1]
__device__ __half g_attnh[MTOT * DE];  // 16 MB
__device__ __half g_hh[MTOT * DE];     // 16 MB, h fp16
__device__ __half g_wqt[DA * DE];      // transposed fp16 weights [n][k]
__device__ __half g_wkt[DA * DE];
__device__ __half g_wvt[DE * DE];
__device__ __half g_wlt[DE * DE];
__device__ float  g_sum[DE];
__device__ float  g_sumsq[DE];

// ================= helpers =================
__device__ __forceinline__ uint32_t smem_to_u32(const void* p) {
    uint32_t a;
    asm("{ .reg .u64 t; cvta.to.shared.u64 t, %1; cvt.u32.u64 %0, t; }" : "=r"(a) : "l"(p));
    return a;
}
__device__ __forceinline__ void mma_f16(float* c, const uint32_t* a,
                                        uint32_t b0, uint32_t b1) {
    asm volatile(
        "mma.sync.aligned.m16n8k16.row.col.f32.f16.f16.f32 "
        "{%0,%1,%2,%3}, {%4,%5,%6,%7}, {%8,%9}, {%0,%1,%2,%3};"
        : "+f"(c[0]), "+f"(c[1]), "+f"(c[2]), "+f"(c[3])
        : "r"(a[0]), "r"(a[1]), "r"(a[2]), "r"(a[3]), "r"(b0), "r"(b1));
}
__device__ __forceinline__ void cp_async16(uint32_t dst, const void* src) {
    asm volatile("cp.async.cg.shared.global [%0], [%1], 16;" :: "r"(dst), "l"(src));
}

// ---------------- fused conversion kernel (x + all weights + BN zero) -------
__global__ void conv_all_kernel(const float* __restrict__ x, __half* __restrict__ xh,
                                const float* __restrict__ Wq, __half* __restrict__ Wqt,
                                const float* __restrict__ Wk, __half* __restrict__ Wkt,
                                const float* __restrict__ Wv, __half* __restrict__ Wvt,
                                const float* __restrict__ Wl, __half* __restrict__ Wlt) {
    const int bidx = blockIdx.x;
    if (bidx < 8192) {
        const int idx = bidx * 256 + threadIdx.x;     // float4 index
        float4 f = ((const float4*)x)[idx];
        ((__half2*)xh)[idx * 2]     = __floats2half2_rn(f.x, f.y);
        ((__half2*)xh)[idx * 2 + 1] = __floats2half2_rn(f.z, f.w);
        return;
    }
    if (bidx == 8192) {
        g_sum[threadIdx.x] = 0.f;
        g_sumsq[threadIdx.x] = 0.f;
    }
    int idx = (bidx - 8192) * 256 + threadIdx.x;   // [0, 163840)
    const float* W; __half* Wt; int N;
    if (idx < 16384)      { W = Wq; Wt = Wqt; N = DA; }
    else if (idx < 32768) { W = Wk; Wt = Wkt; N = DA; idx -= 16384; }
    else if (idx < 98304) { W = Wv; Wt = Wvt; N = DE; idx -= 32768; }
    else                  { W = Wl; Wt = Wlt; N = DE; idx -= 98304; }
    int n = idx >> 8, kk = idx & 255;
    Wt[idx] = __float2half_rn(W[kk * N + n]);
}

// ---------------- fp16 mma.sync GEMM ----------------
// z==0: (Wt0,b0,C0), z==1: (Wt1,b1,C1), z>=2: (Wt2,b2,C2) with bn=(z-2)*64.
// modes: 0 fp16 [row][col] + fused BN stats, 1 fp16 [row][col], 2 fp16 V-interleaved.
#define HA_H (128*72)
#define HW_H (64*72)
#define GEMMH_SMEM ((2*HA_H + 2*HW_H)*2)   // 55296 bytes

__global__ void __launch_bounds__(256)
gemm_f16_kernel(const __half* __restrict__ A,
                const __half* Wt0, const float* b0_, void* C0, int mode01, int Ncols01,
                const __half* Wt1, const float* b1_, void* C1,
                const __half* Wt2, const float* b2_, void* C2) {
    extern __shared__ __half smg[];
    __half* smA = smg;
    __half* smW = smg + 2 * HA_H;
    __shared__ float sred[128];
    const uint32_t sbA = smem_to_u32(smA);
    const uint32_t sbW = smem_to_u32(smW);

    const int z = blockIdx.z;
    const __half* Wt;
    const float* bias;
    void* Cout;
    int mode, Ncols, bn;
    if (z == 0)      { Wt = Wt0; bias = b0_; Cout = C0; mode = mode01; Ncols = Ncols01; bn = blockIdx.y * 64; }
    else if (z == 1) { Wt = Wt1; bias = b1_; Cout = C1; mode = mode01; Ncols = Ncols01; bn = 0; }
    else             { Wt = Wt2; bias = b2_; Cout = C2; mode = 2;      Ncols = 256;     bn = (z - 2) * 64; }

    const int tid = threadIdx.x;
    const int lane = tid & 31, w = tid >> 5;
    const int g = lane >> 2, t = lane & 3;
    const int mw = w >> 1, nw = w & 1;
    const int bm = blockIdx.x * 128;

    if (mode == 0 && tid < 128) sred[tid] = 0.f;

    float c[2][4][4];
    #pragma unroll
    for (int mb = 0; mb < 2; mb++)
        #pragma unroll
        for (int nb = 0; nb < 4; nb++)
            c[mb][nb][0] = c[mb][nb][1] = c[mb][nb][2] = c[mb][nb][3] = 0.f;

    auto issue = [&](int chunk, int stage) {
        const int k0 = chunk * 64;
        #pragma unroll
        for (int i = 0; i < 4; i++) {
            int idx = tid + i * 256;
            int r = idx >> 3, c16 = idx & 7;
            cp_async16(sbA + (uint32_t)(stage * HA_H + r * 72 + c16 * 8) * 2u,
                       A + (size_t)(bm + r) * 256 + k0 + c16 * 8);
        }
        #pragma unroll
        for (int i = 0; i < 2; i++) {
            int idx = tid + i * 256;
            int r = idx >> 3, c16 = idx & 7;
            cp_async16(sbW + (uint32_t)(stage * HW_H + r * 72 + c16 * 8) * 2u,
                       Wt + (size_t)(bn + r) * 256 + k0 + c16 * 8);
        }
    };

    issue(0, 0);
    asm volatile("cp.async.commit_group;" ::: "memory");

    for (int ch = 0; ch < 4; ch++) {
        if (ch + 1 < 4) {
            issue(ch + 1, (ch + 1) & 1);
            asm volatile("cp.async.commit_group;" ::: "memory");
            asm volatile("cp.async.wait_group 1;" ::: "memory");
        } else {
            asm volatile("cp.async.wait_group 0;" ::: "memory");
        }
        __syncthreads();

        const __half* cA = smA + (ch & 1) * HA_H;
        const __half* cW = smW + (ch & 1) * HW_H;

        #pragma unroll
        for (int ks = 0; ks < 4; ks++) {
            uint32_t af[2][4];
            #pragma unroll
            for (int mb = 0; mb < 2; mb++) {
                const __half* p = cA + (mw * 32 + mb * 16 + g) * 72 + ks * 16 + 2 * t;
                af[mb][0] = *(const uint32_t*)p;
                af[mb][1] = *(const uint32_t*)(p + 8 * 72);
                af[mb][2] = *(const uint32_t*)(p + 8);
                af[mb][3] = *(const uint32_t*)(p + 8 * 72 + 8);
            }
            #pragma unroll
            for (int nb = 0; nb < 4; nb++) {
                const __half* p = cW + (nw * 32 + nb * 8 + g) * 72 + ks * 16 + 2 * t;
                uint32_t b0 = *(const uint32_t*)p;
                uint32_t b1 = *(const uint32_t*)(p + 8);
                #pragma unroll
                for (int mb = 0; mb < 2; mb++)
                    mma_f16(c[mb][nb], af[mb], b0, b1);
            }
        }
        __syncthreads();
    }

    if (mode == 2) {
        // stage interleaved tile in smem, then coalesced float4 writes.
        // layout: [rp 0..63][half index (col-bn)*2 + (row&1)], stride 136 halfs
        __half* stg = smA;
        #pragma unroll
        for (int nb = 0; nb < 4; nb++) {
            int colloc = nw * 32 + nb * 8 + 2 * t;
            float bA = bias[bn + colloc], bB = bias[bn + colloc + 1];
            #pragma unroll
            for (int mb = 0; mb < 2; mb++) {
                int lr = mw * 32 + mb * 16 + g;
                int lr2 = lr + 8;
                stg[(lr >> 1) * 136 + colloc * 2 + (lr & 1)]        = __float2half_rn(c[mb][nb][0] + bA);
                stg[(lr >> 1) * 136 + (colloc + 1) * 2 + (lr & 1)]  = __float2half_rn(c[mb][nb][1] + bB);
                stg[(lr2 >> 1) * 136 + colloc * 2 + (lr2 & 1)]      = __float2half_rn(c[mb][nb][2] + bA);
                stg[(lr2 >> 1) * 136 + (colloc + 1) * 2 + (lr2 & 1)] = __float2half_rn(c[mb][nb][3] + bB);
            }
        }
        __syncthreads();
        __half* dst = (__half*)Cout + (size_t)(bm >> 1) * 512 + bn * 2;
        #pragma unroll
        for (int i = 0; i < 4; i++) {              // FIX: 1024 float4s, not 512
            int idx = tid + i * 256;
            int rp = idx >> 4, p4 = idx & 15;
            float4 vv = *(float4*)(stg + rp * 136 + p4 * 8);
            *(float4*)(dst + (size_t)rp * 512 + p4 * 8) = vv;
        }
        return;
    }

    float colsum[4][2] = {}, colsq[4][2] = {};
    #pragma unroll
    for (int nb = 0; nb < 4; nb++) {
        int col = bn + nw * 32 + nb * 8 + 2 * t;
        float b0 = bias[col], b1 = bias[col + 1];
        #pragma unroll
        for (int mb = 0; mb < 2; mb++) {
            int row = bm + mw * 32 + mb * 16 + g;
            float v00 = c[mb][nb][0] + b0, v01 = c[mb][nb][1] + b1;
            float v10 = c[mb][nb][2] + b0, v11 = c[mb][nb][3] + b1;
            __half2* C2 = (__half2*)Cout;
            C2[((size_t)row * Ncols + col) >> 1] = __floats2half2_rn(v00, v01);
            C2[((size_t)(row + 8) * Ncols + col) >> 1] = __floats2half2_rn(v10, v11);
            if (mode == 0) {
                colsum[nb][0] += v00 + v10;
                colsum[nb][1] += v01 + v11;
                colsq[nb][0] += v00 * v00 + v10 * v10;
                colsq[nb][1] += v01 * v01 + v11 * v11;
            }
        }
    }

    if (mode == 0) {
        #pragma unroll
        for (int nb = 0; nb < 4; nb++)
            #pragma unroll
            for (int j = 0; j < 2; j++) {
                float s = colsum[nb][j], q = colsq[nb][j];
                #pragma unroll
                for (int d = 4; d <= 16; d <<= 1) {
                    s += __shfl_xor_sync(0xffffffff, s, d);
                    q += __shfl_xor_sync(0xffffffff, q, d);
                }
                if (g == 0) {
                    int cl = nw * 32 + nb * 8 + 2 * t + j;
                    atomicAdd(&sred[cl * 2],     s);
                    atomicAdd(&sred[cl * 2 + 1], q);
                }
            }
        __syncthreads();
        if (tid < 64) atomicAdd(&g_sum[bn + tid], sred[tid * 2]);
        else if (tid < 128) atomicAdd(&g_sumsq[bn + tid - 64], sred[(tid - 64) * 2 + 1]);
    }
}

// ---------------- pipelined fp16 flash attention (unchanged, proven) -----
#define KSTRH 72
#define KFH   (64*KSTRH)
#define VSTRW 264
#define VFW   (32*VSTRW)
#define STGH  (KFH + 2*VFW)
#define PSTRH 72
#define PFH   (128*PSTRH)
#define NTILES (SEQ/64)
#define ATTN_SMEM (3*STGH*2 + 2*PFH*2 + 256*4)   // 166912 bytes

__global__ void __launch_bounds__(256, 1)
attn_mma_kernel(const __half* __restrict__ q,
                const __half* __restrict__ k,
                const __half* __restrict__ v,
                __half* __restrict__ out) {
    extern __shared__ __half smh[];
    __half* pbuf = smh + 3 * STGH;
    float* smL = (float*)(pbuf + 2 * PFH);
    const uint32_t sbase = smem_to_u32(smh);
    const int tid = threadIdx.x;
    const int lane = tid & 31, w = tid >> 5;
    const int g = lane >> 2, t = lane & 3;
    const int b = blockIdx.y;
    const int q0 = blockIdx.x * 128;

    const int qg = w >> 1, kh = w & 1;
    const int qh = w >> 2, dg = w & 3;

    const __half* kb = k + (size_t)b * SEQ * DA;
    const __half* vb = v + (size_t)b * SEQ * DE;

    uint32_t qa[2][4][4];
    {
        const __half* qbase = q + (size_t)(b * SEQ + q0 + qg * 32) * DA;
        #pragma unroll
        for (int m = 0; m < 2; m++) {
            const __half* r0 = qbase + (size_t)(m * 16 + g) * DA;
            const __half* r8 = r0 + 8 * DA;
            #pragma unroll
            for (int ks = 0; ks < 4; ks++) {
                qa[m][ks][0] = *(const uint32_t*)(r0 + ks * 16 + 2 * t);
                qa[m][ks][1] = *(const uint32_t*)(r8 + ks * 16 + 2 * t);
                qa[m][ks][2] = *(const uint32_t*)(r0 + ks * 16 + 2 * t + 8);
                qa[m][ks][3] = *(const uint32_t*)(r8 + ks * 16 + 2 * t + 8);
            }
        }
    }

    float o[4][8][4];
    #pragma unroll
    for (int m = 0; m < 4; m++)
        #pragma unroll
        for (int nb = 0; nb < 8; nb++)
            o[m][nb][0] = o[m][nb][1] = o[m][nb][2] = o[m][nb][3] = 0.f;
    float rs[2][2] = {{0.f, 0.f}, {0.f, 0.f}};

    auto issue = [&](int tile, int stage) {
        const uint32_t kd = sbase + (uint32_t)(stage * STGH) * 2u;
        const uint32_t vd = kd + (uint32_t)KFH * 2u;
        const __half* ksrc = kb + (size_t)tile * 64 * DA;
        const __half* vsrc = vb + (size_t)tile * 32 * 512;
        #pragma unroll
        for (int i = 0; i < 2; i++) {
            int idx = tid + i * 256;
            int r = idx >> 3, c16 = idx & 7;
            cp_async16(kd + (uint32_t)(r * KSTRH * 2 + c16 * 16), ksrc + r * 64 + c16 * 8);
        }
        #pragma unroll
        for (int i = 0; i < 8; i++) {
            int idx = tid + i * 256;
            int r = idx >> 6, ch = idx & 63;
            cp_async16(vd + (uint32_t)(r * VSTRW * 4 + ch * 16), vsrc + (size_t)r * 512 + ch * 8);
        }
    };

    auto do_S_exp = [&](int tile) {
        const __half* sK = smh + (tile % 3) * STGH;
        float c[2][4][4];
        #pragma unroll
        for (int m = 0; m < 2; m++)
            #pragma unroll
            for (int nb = 0; nb < 4; nb++)
                c[m][nb][0] = c[m][nb][1] = c[m][nb][2] = c[m][nb][3] = 0.f;
        #pragma unroll
        for (int ks = 0; ks < 4; ks++) {
            #pragma unroll
            for (int nb = 0; nb < 4; nb++) {
                const __half* kr = sK + (kh * 32 + nb * 8 + g) * KSTRH + ks * 16 + 2 * t;
                uint32_t b0 = *(const uint32_t*)kr;
                uint32_t b1 = *(const uint32_t*)(kr + 8);
                mma_f16(c[0][nb], qa[0][ks], b0, b1);
                mma_f16(c[1][nb], qa[1][ks], b0, b1);
            }
        }
        __half* smPn = pbuf + (tile & 1) * PFH;
        #pragma unroll
        for (int m = 0; m < 2; m++) {
            __half* pr = smPn + (qg * 32 + m * 16 + g) * PSTRH + kh * 32;
            __half* pr8 = pr + 8 * PSTRH;
            #pragma unroll
            for (int nb = 0; nb < 4; nb++) {
                float e0 = __expf(c[m][nb][0] * 0.015625f);
                float e1 = __expf(c[m][nb][1] * 0.015625f);
                float e2 = __expf(c[m][nb][2] * 0.015625f);
                float e3 = __expf(c[m][nb][3] * 0.015625f);
                rs[m][0] += e0 + e1;
                rs[m][1] += e2 + e3;
                *(__half2*)(pr + nb * 8 + 2 * t) = __floats2half2_rn(e0, e1);
                *(__half2*)(pr8 + nb * 8 + 2 * t) = __floats2half2_rn(e2, e3);
            }
        }
    };

    issue(0, 0);
    asm volatile("cp.async.commit_group;" ::: "memory");
    issue(1, 1);
    asm volatile("cp.async.commit_group;" ::: "memory");
    asm volatile("cp.async.wait_group 1;" ::: "memory");
    __syncthreads();
    do_S_exp(0);

    for (int i = 0; i < NTILES; i++) {
        if (i + 1 < NTILES) asm volatile("cp.async.wait_group 0;" ::: "memory");
        __syncthreads();
        if (i + 2 < NTILES) {
            issue(i + 2, (i + 2) % 3);
            asm volatile("cp.async.commit_group;" ::: "memory");
        }

        if (i + 1 < NTILES) do_S_exp(i + 1);

        {
            const uint32_t* sVw = (const uint32_t*)(smh + (i % 3) * STGH + KFH);
            const __half* smPc = pbuf + (i & 1) * PFH;
            #pragma unroll
            for (int ks = 0; ks < 4; ks++) {
                uint32_t pf[4][4];
                #pragma unroll
                for (int m = 0; m < 4; m++) {
                    const __half* p0 = smPc + (qh * 64 + m * 16 + g) * PSTRH + ks * 16 + 2 * t;
                    pf[m][0] = *(const uint32_t*)p0;
                    pf[m][1] = *(const uint32_t*)(p0 + 8 * PSTRH);
                    pf[m][2] = *(const uint32_t*)(p0 + 8);
                    pf[m][3] = *(const uint32_t*)(p0 + 8 * PSTRH + 8);
                }
                #pragma unroll
                for (int nb = 0; nb < 8; nb++) {
                    const uint32_t* vw = sVw + (ks * 8 + t) * VSTRW + dg * 64 + nb * 8 + g;
                    uint32_t b0 = vw[0];
                    uint32_t b1 = vw[4 * VSTRW];
                    #pragma unroll
                    for (int m = 0; m < 4; m++)
                        mma_f16(o[m][nb], pf[m], b0, b1);
                }
            }
        }
    }

    #pragma unroll
    for (int m = 0; m < 2; m++)
        #pragma unroll
        for (int r = 0; r < 2; r++) {
            rs[m][r] += __shfl_xor_sync(0xffffffff, rs[m][r], 1);
            rs[m][r] += __shfl_xor_sync(0xffffffff, rs[m][r], 2);
        }
    if (t == 0) {
        #pragma unroll
        for (int m = 0; m < 2; m++)
            #pragma unroll
            for (int r = 0; r < 2; r++)
                smL[kh * 128 + qg * 32 + m * 16 + r * 8 + g] = rs[m][r];
    }
    __syncthreads();

    #pragma unroll
    for (int m = 0; m < 4; m++) {
        int qrow = qh * 64 + m * 16 + g;
        float inv0 = 1.f / (smL[qrow] + smL[128 + qrow]);
        float inv8 = 1.f / (smL[qrow + 8] + smL[128 + qrow + 8]);
        __half* out0 = out + (size_t)(b * SEQ + q0 + qrow) * DE + dg * 64;
        __half* out8 = out0 + 8 * DE;
        #pragma unroll
        for (int nb = 0; nb < 8; nb++) {
            *(__half2*)(out0 + nb * 8 + 2 * t) =
                __floats2half2_rn(o[m][nb][0] * inv0, o[m][nb][1] * inv0);
            *(__half2*)(out8 + nb * 8 + 2 * t) =
                __floats2half2_rn(o[m][nb][2] * inv8, o[m][nb][3] * inv8);
        }
    }
}

// ---------------- BN finalize (fp16 h) ----------------
__global__ void bn_finalize_kernel(const __half* __restrict__ h,
                                   const float* __restrict__ x,
                                   const float* __restrict__ gamma,
                                   const float* __restrict__ beta,
                                   float* __restrict__ y) {
    const int idx = blockIdx.x * 256 + threadIdx.x;   // group of 4 elems
    const int c0 = (idx * 4) & 255;
    const float invM = 1.f / (float)MTOT;
    uint2 hr = ((const uint2*)h)[idx];
    __half2 ha = *(__half2*)&hr.x;
    __half2 hb = *(__half2*)&hr.y;
    float4 xv = ((const float4*)x)[idx];
    float hvv[4] = {__low2float(ha), __high2float(ha), __low2float(hb), __high2float(hb)};
    float xvv[4] = {xv.x, xv.y, xv.z, xv.w};
    float r[4];
    #pragma unroll
    for (int u = 0; u < 4; u++) {
        int c = c0 + u;
        float mean = g_sum[c] * invM;
        float var = g_sumsq[c] * invM - mean * mean;
        float rsv = rsqrtf(var + 1e-5f);
        float val = (hvv[u] - mean) * rsv * gamma[c] + beta[c];
        r[u] = fmaxf(val, 0.f) + xvv[u];
    }
    float4 ov = {r[0], r[1], r[2], r[3]};
    ((float4*)y)[idx] = ov;
}

// ---------------- launch ----------------
extern "C" void kernel_launch(void* const* d_in, const int* in_sizes, int n_in,
                              void* d_out, int out_size) {
    const float* x     = (const float*)d_in[0];
    const float* Wq    = (const float*)d_in[1];
    const float* bq    = (const float*)d_in[2];
    const float* Wk    = (const float*)d_in[3];
    const float* bk    = (const float*)d_in[4];
    const float* Wv    = (const float*)d_in[5];
    const float* bv    = (const float*)d_in[6];
    const float* Wl    = (const float*)d_in[7];
    const float* bl    = (const float*)d_in[8];
    const float* gamma = (const float*)d_in[9];
    const float* beta  = (const float*)d_in[10];
    float* out = (float*)d_out;

    __half *pxh, *pqh, *pkh, *pvh, *pattnh, *phh, *pwqt, *pwkt, *pwvt, *pwlt;
    cudaGetSymbolAddress((void**)&pxh, g_xh);
    cudaGetSymbolAddress((void**)&pqh, g_qh);
    cudaGetSymbolAddress((void**)&pkh, g_kh);
    cudaGetSymbolAddress((void**)&pvh, g_vh);
    cudaGetSymbolAddress((void**)&pattnh, g_attnh);
    cudaGetSymbolAddress((void**)&phh, g_hh);
    cudaGetSymbolAddress((void**)&pwqt, g_wqt);
    cudaGetSymbolAddress((void**)&pwkt, g_wkt);
    cudaGetSymbolAddress((void**)&pwvt, g_wvt);
    cudaGetSymbolAddress((void**)&pwlt, g_wlt);

    cudaFuncSetAttribute(attn_mma_kernel, cudaFuncAttributeMaxDynamicSharedMemorySize,
                         ATTN_SMEM);
    cudaFuncSetAttribute(gemm_f16_kernel, cudaFuncAttributeMaxDynamicSharedMemorySize,
                         GEMMH_SMEM);

    // conversions + BN zeroing (1 launch)
    conv_all_kernel<<<8192 + 640, 256>>>(x, pxh, Wq, pwqt, Wk, pwkt, Wv, pwvt, Wl, pwlt);

    // all projections in ONE launch: z0=q, z1=k, z2..5=v
    gemm_f16_kernel<<<dim3(MTOT / 128, 1, 6), 256, GEMMH_SMEM>>>(
        pxh,
        pwqt, bq, pqh, /*mode01=*/1, /*Ncols01=*/DA,
        pwkt, bk, pkh,
        pwvt, bv, pvh);

    // attention (pipelined fp16 m16n8k16)
    attn_mma_kernel<<<dim3(SEQ / 128, BATCH), 256, ATTN_SMEM>>>(pqh, pkh, pvh, pattnh);

    // h = attn @ Wl + bl (fp16 out) + fused BN stats
    gemm_f16_kernel<<<dim3(MTOT / 128, 4, 1), 256, GEMMH_SMEM>>>(
        pattnh,
        pwlt, bl, phh, /*mode01=*/0, /*Ncols01=*/DE,
        pwlt, bl, phh,
        pwlt, bl, phh);

    // batchnorm finalize + relu + residual
    bn_finalize_kernel<<<(MTOT * DE) / 4 / 256, 256>>>(phh, x, gamma, beta, out);
}